// round 11
// baseline (speedup 1.0000x reference)
#include <cuda_runtime.h>

#define D_MODEL 1024
#define SEQ     2048
#define BATCH   2
#define NH      16
#define DH      64
#define MROWS   (BATCH * SEQ)   /* 4096 */

typedef unsigned long long u64;

// ---------------- packed fp32x2 helpers (Blackwell fma.rn.f32x2) -------------
__device__ __forceinline__ u64 f2pack(float lo, float hi) {
    u64 r; asm("mov.b64 %0,{%1,%2};" : "=l"(r) : "f"(lo), "f"(hi)); return r;
}
__device__ __forceinline__ u64 f2dup(float v) {
    u64 r; asm("mov.b64 %0,{%1,%1};" : "=l"(r) : "f"(v)); return r;
}
__device__ __forceinline__ void f2fma(u64& d, u64 a, u64 b) {
    asm("fma.rn.f32x2 %0,%1,%2,%0;" : "+l"(d) : "l"(a), "l"(b));
}
__device__ __forceinline__ u64 f2mul(u64 a, u64 b) {
    u64 r; asm("mul.rn.f32x2 %0,%1,%2;" : "=l"(r) : "l"(a), "l"(b)); return r;
}
__device__ __forceinline__ void f2unpack(u64 v, float& lo, float& hi) {
    asm("mov.b64 {%0,%1},%2;" : "=f"(lo), "=f"(hi) : "l"(v));
}

// ---------------- scratch (static device arrays; no runtime allocation) -----
__device__ float g_W[4][D_MODEL * D_MODEL];   // q,k,v,o dense weights (out,in)
__device__ float g_Qp[MROWS * D_MODEL];
__device__ float g_Kp[MROWS * D_MODEL];
__device__ float g_Vp[MROWS * D_MODEL];
__device__ float g_AO[MROWS * D_MODEL];       // attention output, [b,s,h*64+d]

// ---------------- TT cores -> dense W ---------------------------------------
__global__ void build_w_kernel(const float* __restrict__ g0,
                               const float* __restrict__ g1,
                               int wsel)
{
    int idx = blockIdx.x * blockDim.x + threadIdx.x;   // over 1024*1024
    int n = idx >> 10;
    int k = idx & 1023;
    int i1 = n >> 5, i2 = n & 31;
    int j1 = k >> 5, j2 = k & 31;
    const float* a = &g0[(i1 * 32 + j1) * 8];
    float s = 0.f;
#pragma unroll
    for (int r = 0; r < 8; r++)
        s += a[r] * g1[(r * 32 + i2) * 32 + j2];
    g_W[wsel][idx] = s;
}

// ---------------- GEMM: Y[M,1024] = X[M,1024] @ W^T + bias ------------------
// BM=BN=128, BK=8, 256 threads, 8x8 per thread. Inner product uses packed
// fp32x2 FMA: accumulators pair adjacent output columns (dup-A x pair-B).
#define BM 128
#define BN 128
#define BK 8

__global__ __launch_bounds__(256)
void gemm_kernel(const float* __restrict__ Xext, int xsel, int wsel,
                 const float* __restrict__ bias,
                 float* __restrict__ Yext, int ysel)
{
    const float* X = (xsel == 3) ? g_AO : Xext;
    const float* W = g_W[wsel];
    float* Y = (ysel == 0) ? g_Qp : (ysel == 1) ? g_Kp
             : (ysel == 2) ? g_Vp : Yext;

    __shared__ float Xs[BK][BM];   // transposed: Xs[k][m]
    __shared__ float Ws[BK][BN];   // transposed: Ws[k][n]

    int tid = threadIdx.x;
    int tx = tid & 15, ty = tid >> 4;
    int bm = blockIdx.y * BM;
    int bn = blockIdx.x * BN;

    int lr = tid >> 1;            // 0..127 : row within tile
    int lk = (tid & 1) << 2;      // 0 or 4 : k offset (float4)

    const float* Xp = X + (size_t)(bm + lr) * D_MODEL + lk;
    const float* Wp = W + (size_t)(bn + lr) * D_MODEL + lk;

    u64 acc2[8][4];               // [row][col-pair]: (2*j2, 2*j2+1)
#pragma unroll
    for (int i = 0; i < 8; i++)
#pragma unroll
        for (int j = 0; j < 4; j++) acc2[i][j] = 0ull;

    for (int k0 = 0; k0 < D_MODEL; k0 += BK) {
        float4 xv = *(const float4*)(Xp + k0);
        float4 wv = *(const float4*)(Wp + k0);
        Xs[lk + 0][lr] = xv.x; Xs[lk + 1][lr] = xv.y;
        Xs[lk + 2][lr] = xv.z; Xs[lk + 3][lr] = xv.w;
        Ws[lk + 0][lr] = wv.x; Ws[lk + 1][lr] = wv.y;
        Ws[lk + 2][lr] = wv.z; Ws[lk + 3][lr] = wv.w;
        __syncthreads();
#pragma unroll
        for (int kk = 0; kk < BK; kk++) {
            float a[8], b[8];
            *(float4*)&a[0] = *(const float4*)&Xs[kk][4 * ty];
            *(float4*)&a[4] = *(const float4*)&Xs[kk][64 + 4 * ty];
            *(float4*)&b[0] = *(const float4*)&Ws[kk][4 * tx];
            *(float4*)&b[4] = *(const float4*)&Ws[kk][64 + 4 * tx];
            u64 ad[8], bp[4];
#pragma unroll
            for (int i = 0; i < 8; i++) ad[i] = f2dup(a[i]);
#pragma unroll
            for (int j = 0; j < 4; j++) bp[j] = f2pack(b[2 * j], b[2 * j + 1]);
#pragma unroll
            for (int i = 0; i < 8; i++)
#pragma unroll
                for (int j = 0; j < 4; j++)
                    f2fma(acc2[i][j], ad[i], bp[j]);
        }
        __syncthreads();
    }

#pragma unroll
    for (int ih = 0; ih < 2; ih++) {
#pragma unroll
        for (int i = 0; i < 4; i++) {
            int row = bm + ih * 64 + 4 * ty + i;
#pragma unroll
            for (int jh = 0; jh < 2; jh++) {
                int col = bn + jh * 64 + 4 * tx;
                float lo0, hi0, lo1, hi1;
                f2unpack(acc2[ih * 4 + i][jh * 2 + 0], lo0, hi0);
                f2unpack(acc2[ih * 4 + i][jh * 2 + 1], lo1, hi1);
                float4 r;
                r.x = lo0 + bias[col + 0];
                r.y = hi0 + bias[col + 1];
                r.z = lo1 + bias[col + 2];
                r.w = hi1 + bias[col + 3];
                *(float4*)(Y + (size_t)row * D_MODEL + col) = r;
            }
        }
    }
}

// ---------------- Flash attention (packed fp32x2 math) -----------------------
// QK^T: accumulators pack (even-d, odd-d) partial dots, merged before softmax.
// PV:   O accumulators pack (even-kk, odd-kk) partial sums, kept packed across
//       tiles (alpha rescale is packed too), merged only at the final write.
__global__ __launch_bounds__(256)
void flash_kernel()
{
    __shared__ float Qs[64 * 64];
    __shared__ float KPs[64 * 64];   // union: swizzled K tile, then P tile
    __shared__ float Vs[64 * 64];

    int tid = threadIdx.x;
    int tx = tid & 15, ty = tid >> 4;
    int b = blockIdx.z, h = blockIdx.y;
    int qb = blockIdx.x * 64;

    const float* Qg = g_Qp + (size_t)b * SEQ * D_MODEL + h * DH;
    const float* Kg = g_Kp + (size_t)b * SEQ * D_MODEL + h * DH;
    const float* Vg = g_Vp + (size_t)b * SEQ * D_MODEL + h * DH;

    int f4 = tid & 15;    // float4 group along d
    int r0 = tid >> 4;    // base row

    // load Q tile, fold 1/sqrt(64) scale
#pragma unroll
    for (int it = 0; it < 4; it++) {
        int r = r0 + 16 * it;
        float4 v = *(const float4*)(Qg + (size_t)(qb + r) * D_MODEL + f4 * 4);
        v.x *= 0.125f; v.y *= 0.125f; v.z *= 0.125f; v.w *= 0.125f;
        *(float4*)&Qs[r * 64 + f4 * 4] = v;
    }

    float m[4], l[4];
    u64 o2[4][4];         // packed (even-kk, odd-kk) partial sums
#pragma unroll
    for (int i = 0; i < 4; i++) {
        m[i] = -1e30f; l[i] = 0.f;
#pragma unroll
        for (int j = 0; j < 4; j++) o2[i][j] = 0ull;
    }

    for (int kt = 0; kt < SEQ; kt += 64) {
        __syncthreads();   // previous PV / P reads done before overwrite
#pragma unroll
        for (int it = 0; it < 4; it++) {
            int r = r0 + 16 * it;
            float4 kv = *(const float4*)(Kg + (size_t)(kt + r) * D_MODEL + f4 * 4);
            int slot = (f4 + r + (r >> 2)) & 15;
            *(float4*)&KPs[r * 64 + slot * 4] = kv;
            float4 vv = *(const float4*)(Vg + (size_t)(kt + r) * D_MODEL + f4 * 4);
            *(float4*)&Vs[r * 64 + f4 * 4] = vv;
        }
        __syncthreads();

        // ---- S = Q K^T (Q pre-scaled), packed along d ----
        u64 s2[4][4];
#pragma unroll
        for (int i = 0; i < 4; i++)
#pragma unroll
            for (int j = 0; j < 4; j++) s2[i][j] = 0ull;

#pragma unroll
        for (int d4 = 0; d4 < 16; d4++) {
            float4 a0 = *(const float4*)&Qs[(4 * ty + 0) * 64 + d4 * 4];
            float4 a1 = *(const float4*)&Qs[(4 * ty + 1) * 64 + d4 * 4];
            float4 a2 = *(const float4*)&Qs[(4 * ty + 2) * 64 + d4 * 4];
            float4 a3 = *(const float4*)&Qs[(4 * ty + 3) * 64 + d4 * 4];
            u64 ap[4][2];
            ap[0][0] = f2pack(a0.x, a0.y); ap[0][1] = f2pack(a0.z, a0.w);
            ap[1][0] = f2pack(a1.x, a1.y); ap[1][1] = f2pack(a1.z, a1.w);
            ap[2][0] = f2pack(a2.x, a2.y); ap[2][1] = f2pack(a2.z, a2.w);
            ap[3][0] = f2pack(a3.x, a3.y); ap[3][1] = f2pack(a3.z, a3.w);
#pragma unroll
            for (int j = 0; j < 4; j++) {
                int kj = 4 * tx + j;
                int slot = (d4 + kj + tx) & 15;   // kj>>2 == tx for j<4
                float4 bb = *(const float4*)&KPs[kj * 64 + slot * 4];
                u64 bp0 = f2pack(bb.x, bb.y);
                u64 bp1 = f2pack(bb.z, bb.w);
#pragma unroll
                for (int i = 0; i < 4; i++) {
                    f2fma(s2[i][j], ap[i][0], bp0);
                    f2fma(s2[i][j], ap[i][1], bp1);
                }
            }
        }

        float s[4][4];
#pragma unroll
        for (int i = 0; i < 4; i++)
#pragma unroll
            for (int j = 0; j < 4; j++) {
                float lo, hi; f2unpack(s2[i][j], lo, hi);
                s[i][j] = lo + hi;
            }

        // ---- online softmax (row reductions across the 16 tx lanes) ----
#pragma unroll
        for (int i = 0; i < 4; i++) {
            float mt = fmaxf(fmaxf(s[i][0], s[i][1]), fmaxf(s[i][2], s[i][3]));
            mt = fmaxf(mt, __shfl_xor_sync(0xffffffffu, mt, 1));
            mt = fmaxf(mt, __shfl_xor_sync(0xffffffffu, mt, 2));
            mt = fmaxf(mt, __shfl_xor_sync(0xffffffffu, mt, 4));
            mt = fmaxf(mt, __shfl_xor_sync(0xffffffffu, mt, 8));
            float mn = fmaxf(m[i], mt);
            float alpha = __expf(m[i] - mn);
            m[i] = mn;
            float rs = 0.f;
#pragma unroll
            for (int j = 0; j < 4; j++) {
                s[i][j] = __expf(s[i][j] - mn);
                rs += s[i][j];
            }
            rs += __shfl_xor_sync(0xffffffffu, rs, 1);
            rs += __shfl_xor_sync(0xffffffffu, rs, 2);
            rs += __shfl_xor_sync(0xffffffffu, rs, 4);
            rs += __shfl_xor_sync(0xffffffffu, rs, 8);
            l[i] = l[i] * alpha + rs;
            u64 av = f2dup(alpha);
#pragma unroll
            for (int j = 0; j < 4; j++) o2[i][j] = f2mul(o2[i][j], av);
        }

        __syncthreads();   // everyone done reading K before P overwrites it
#pragma unroll
        for (int i = 0; i < 4; i++) {
            float4 pr; pr.x = s[i][0]; pr.y = s[i][1]; pr.z = s[i][2]; pr.w = s[i][3];
            *(float4*)&KPs[(4 * ty + i) * 64 + 4 * tx] = pr;
        }
        __syncthreads();

        // ---- O += P V, packed along kk-parity ----
#pragma unroll
        for (int k4 = 0; k4 < 16; k4++) {
            float4 p0 = *(const float4*)&KPs[(4 * ty + 0) * 64 + k4 * 4];
            float4 p1 = *(const float4*)&KPs[(4 * ty + 1) * 64 + k4 * 4];
            float4 p2 = *(const float4*)&KPs[(4 * ty + 2) * 64 + k4 * 4];
            float4 p3 = *(const float4*)&KPs[(4 * ty + 3) * 64 + k4 * 4];
            float4 v0 = *(const float4*)&Vs[(k4 * 4 + 0) * 64 + 4 * tx];
            float4 v1 = *(const float4*)&Vs[(k4 * 4 + 1) * 64 + 4 * tx];
            float4 v2 = *(const float4*)&Vs[(k4 * 4 + 2) * 64 + 4 * tx];
            float4 v3 = *(const float4*)&Vs[(k4 * 4 + 3) * 64 + 4 * tx];

            u64 pp[4][2];
            pp[0][0] = f2pack(p0.x, p0.y); pp[0][1] = f2pack(p0.z, p0.w);
            pp[1][0] = f2pack(p1.x, p1.y); pp[1][1] = f2pack(p1.z, p1.w);
            pp[2][0] = f2pack(p2.x, p2.y); pp[2][1] = f2pack(p2.z, p2.w);
            pp[3][0] = f2pack(p3.x, p3.y); pp[3][1] = f2pack(p3.z, p3.w);

            u64 vp0[4], vp1[4];   // [j]: (V[kk0][j],V[kk1][j]) and (V[kk2][j],V[kk3][j])
            vp0[0] = f2pack(v0.x, v1.x); vp1[0] = f2pack(v2.x, v3.x);
            vp0[1] = f2pack(v0.y, v1.y); vp1[1] = f2pack(v2.y, v3.y);
            vp0[2] = f2pack(v0.z, v1.z); vp1[2] = f2pack(v2.z, v3.z);
            vp0[3] = f2pack(v0.w, v1.w); vp1[3] = f2pack(v2.w, v3.w);

#pragma unroll
            for (int i = 0; i < 4; i++)
#pragma unroll
                for (int j = 0; j < 4; j++) {
                    f2fma(o2[i][j], pp[i][0], vp0[j]);
                    f2fma(o2[i][j], pp[i][1], vp1[j]);
                }
        }
    }

    // merge packed halves, normalize, write to [b, s, h*64 + d]
    float* Og = g_AO + (size_t)b * SEQ * D_MODEL + h * DH;
#pragma unroll
    for (int i = 0; i < 4; i++) {
        float inv = 1.f / l[i];
        float oo[4];
#pragma unroll
        for (int j = 0; j < 4; j++) {
            float lo, hi; f2unpack(o2[i][j], lo, hi);
            oo[j] = (lo + hi) * inv;
        }
        float4 r; r.x = oo[0]; r.y = oo[1]; r.z = oo[2]; r.w = oo[3];
        *(float4*)(Og + (size_t)(qb + 4 * ty + i) * D_MODEL + 4 * tx) = r;
    }
}

// ---------------- launch ------------------------------------------------------
extern "C" void kernel_launch(void* const* d_in, const int* in_sizes, int n_in,
                              void* d_out, int out_size)
{
    (void)in_sizes; (void)n_in; (void)out_size;
    const float* query = (const float*)d_in[0];
    const float* key   = (const float*)d_in[1];
    const float* value = (const float*)d_in[2];

    // TT cores -> dense W (q,k,v,o)
    build_w_kernel<<<4096, 256>>>((const float*)d_in[3],  (const float*)d_in[4],  0);
    build_w_kernel<<<4096, 256>>>((const float*)d_in[6],  (const float*)d_in[7],  1);
    build_w_kernel<<<4096, 256>>>((const float*)d_in[9],  (const float*)d_in[10], 2);
    build_w_kernel<<<4096, 256>>>((const float*)d_in[12], (const float*)d_in[13], 3);

    dim3 gg(D_MODEL / BN, MROWS / BM);   // (8, 32)
    gemm_kernel<<<gg, 256>>>(query, 0, 0, (const float*)d_in[5],  nullptr, 0);
    gemm_kernel<<<gg, 256>>>(key,   1, 1, (const float*)d_in[8],  nullptr, 1);
    gemm_kernel<<<gg, 256>>>(value, 2, 2, (const float*)d_in[11], nullptr, 2);

    flash_kernel<<<dim3(SEQ / 64, NH, BATCH), 256>>>();

    gemm_kernel<<<gg, 256>>>(nullptr, 3, 3, (const float*)d_in[14],
                             (float*)d_out, 3);
}

// round 13
// speedup vs baseline: 2.1423x; 2.1423x over previous
#include <cuda_runtime.h>
#include <cuda_bf16.h>

#define D_MODEL 1024
#define SEQ     2048
#define BATCH   2
#define NH      16
#define DH      64
#define MROWS   4096

typedef unsigned int u32;

// ---------------- helpers ----------------------------------------------------
__device__ __forceinline__ u32 pk2(float lo, float hi) {
    __nv_bfloat162 t = __floats2bfloat162_rn(lo, hi);   // lo -> .x (low half)
    return *reinterpret_cast<u32*>(&t);
}
__device__ __forceinline__ float split_hi(float x, float& lo) {
    float h = __bfloat162float(__float2bfloat16(x));
    lo = x - h;
    return h;
}
__device__ __forceinline__ void mma16816(float* c,
                                         u32 a0, u32 a1, u32 a2, u32 a3,
                                         u32 b0, u32 b1) {
    asm volatile(
        "mma.sync.aligned.m16n8k16.row.col.f32.bf16.bf16.f32 "
        "{%0,%1,%2,%3},{%4,%5,%6,%7},{%8,%9},{%0,%1,%2,%3};"
        : "+f"(c[0]), "+f"(c[1]), "+f"(c[2]), "+f"(c[3])
        : "r"(a0), "r"(a1), "r"(a2), "r"(a3), "r"(b0), "r"(b1));
}

// ---------------- scratch (static; no runtime allocation) --------------------
// bf16 PAIRS packed in u32: index = row*512 + col/2
__device__ u32 g_Wh[4][D_MODEL * 512];
__device__ u32 g_Wl[4][D_MODEL * 512];
__device__ u32 g_Qh[MROWS * 512], g_Ql[MROWS * 512];
__device__ u32 g_Kh[MROWS * 512], g_Kl[MROWS * 512];
__device__ u32 g_Vh[MROWS * 512], g_Vl[MROWS * 512];
__device__ float g_AO[MROWS * D_MODEL];

// ---------------- TT cores -> dense W (split bf16 hi/lo) ---------------------
__global__ void build_w_kernel(const float* __restrict__ g0,
                               const float* __restrict__ g1,
                               int wsel)
{
    int idx = blockIdx.x * 256 + threadIdx.x;   // over 1024*512 pairs
    int n  = idx >> 9;
    int k  = (idx & 511) * 2;
    int i1 = n >> 5, i2 = n & 31;
    int j1 = k >> 5, j2 = k & 31;               // k even -> k,k+1 share j1
    const float* a = &g0[(i1 * 32 + j1) * 8];
    float s0 = 0.f, s1 = 0.f;
#pragma unroll
    for (int r = 0; r < 8; r++) {
        const float* g1p = &g1[(r * 32 + i2) * 32 + j2];
        s0 += a[r] * g1p[0];
        s1 += a[r] * g1p[1];
    }
    float l0, l1;
    float h0 = split_hi(s0, l0), h1 = split_hi(s1, l1);
    g_Wh[wsel][idx] = pk2(h0, h1);
    g_Wl[wsel][idx] = pk2(l0, l1);
}

// ---------------- GEMM: Y[M,1024] = X[M,1024] @ W^T + bias  (HMMA) ----------
// 128x128x32 tile, 256 threads = 8 warps of 64x32. smem pitch 20 u32 (40 bf16)
// -> verified conflict-free fragment LDS.
#define GP 20   /* smem row pitch in u32 pairs */

__global__ __launch_bounds__(256)
void gemm_kernel(const float* __restrict__ Xext, int xsel, int wsel,
                 const float* __restrict__ bias, float outscale,
                 float* __restrict__ Yout, int ysel)
{
    const float* X = (xsel == 3) ? g_AO : Xext;
    const u32* Wh = g_Wh[wsel];
    const u32* Wl = g_Wl[wsel];
    u32* Yh = (ysel == 0) ? g_Qh : (ysel == 1) ? g_Kh : g_Vh;
    u32* Yl = (ysel == 0) ? g_Ql : (ysel == 1) ? g_Kl : g_Vl;

    __shared__ u32 Ah[128 * GP], Al[128 * GP], Bh[128 * GP], Bl[128 * GP];

    int tid  = threadIdx.x;
    int lane = tid & 31;
    int warp = tid >> 5;
    int wm = warp & 1, wn = warp >> 1;
    int bm = blockIdx.y * 128, bn = blockIdx.x * 128;

    int lr = tid >> 1;          // 0..127 row
    int lh = tid & 1;           // k-half (16 k each)

    float c[4][4][4];
#pragma unroll
    for (int i = 0; i < 4; i++)
#pragma unroll
        for (int j = 0; j < 4; j++)
#pragma unroll
            for (int e = 0; e < 4; e++) c[i][j][e] = 0.f;

    const float* Xp = X + (size_t)(bm + lr) * D_MODEL + lh * 16;
    const u32* Whp = Wh + (size_t)(bn + lr) * 512 + lh * 8;
    const u32* Wlp = Wl + (size_t)(bn + lr) * 512 + lh * 8;
    u32* As_h = &Ah[lr * GP + lh * 8];
    u32* As_l = &Al[lr * GP + lh * 8];
    u32* Bs_h = &Bh[lr * GP + lh * 8];
    u32* Bs_l = &Bl[lr * GP + lh * 8];

    for (int k0 = 0; k0 < D_MODEL; k0 += 32) {
        // stage A (fp32 -> split bf16 pairs)
        u32 hb[8], lb[8];
#pragma unroll
        for (int j = 0; j < 4; j++) {
            float4 x = *(const float4*)(Xp + k0 + 4 * j);
            float l0, l1, l2, l3;
            float h0 = split_hi(x.x, l0), h1 = split_hi(x.y, l1);
            float h2 = split_hi(x.z, l2), h3 = split_hi(x.w, l3);
            hb[2 * j] = pk2(h0, h1); hb[2 * j + 1] = pk2(h2, h3);
            lb[2 * j] = pk2(l0, l1); lb[2 * j + 1] = pk2(l2, l3);
        }
        *(uint4*)(As_h)     = *(uint4*)&hb[0];
        *(uint4*)(As_h + 4) = *(uint4*)&hb[4];
        *(uint4*)(As_l)     = *(uint4*)&lb[0];
        *(uint4*)(As_l + 4) = *(uint4*)&lb[4];
        // stage B (already split in gmem)
        *(uint4*)(Bs_h)     = *(const uint4*)(Whp + (k0 >> 1));
        *(uint4*)(Bs_h + 4) = *(const uint4*)(Whp + (k0 >> 1) + 4);
        *(uint4*)(Bs_l)     = *(const uint4*)(Wlp + (k0 >> 1));
        *(uint4*)(Bs_l + 4) = *(const uint4*)(Wlp + (k0 >> 1) + 4);
        __syncthreads();

#pragma unroll
        for (int ks = 0; ks < 2; ks++) {
            int aw = (wm * 64 + (lane >> 2)) * GP + ks * 8 + (lane & 3);
            u32 ah[4][4], al[4][4];
#pragma unroll
            for (int i = 0; i < 4; i++) {
                int b0 = aw + i * 16 * GP;
                ah[i][0] = Ah[b0];            ah[i][1] = Ah[b0 + 8 * GP];
                ah[i][2] = Ah[b0 + 4];        ah[i][3] = Ah[b0 + 8 * GP + 4];
                al[i][0] = Al[b0];            al[i][1] = Al[b0 + 8 * GP];
                al[i][2] = Al[b0 + 4];        al[i][3] = Al[b0 + 8 * GP + 4];
            }
            int bw = (wn * 32 + (lane >> 2)) * GP + ks * 8 + (lane & 3);
#pragma unroll
            for (int j = 0; j < 4; j++) {
                int b0 = bw + j * 8 * GP;
                u32 bh0 = Bh[b0], bh1 = Bh[b0 + 4];
                u32 bl0 = Bl[b0], bl1 = Bl[b0 + 4];
#pragma unroll
                for (int i = 0; i < 4; i++) {
                    mma16816(c[i][j], ah[i][0], ah[i][1], ah[i][2], ah[i][3], bh0, bh1);
                    mma16816(c[i][j], ah[i][0], ah[i][1], ah[i][2], ah[i][3], bl0, bl1);
                    mma16816(c[i][j], al[i][0], al[i][1], al[i][2], al[i][3], bh0, bh1);
                }
            }
        }
        __syncthreads();
    }

    // epilogue
#pragma unroll
    for (int i = 0; i < 4; i++) {
#pragma unroll
        for (int j = 0; j < 4; j++) {
            int row = bm + wm * 64 + i * 16 + (lane >> 2);
            int col = bn + wn * 32 + j * 8 + (lane & 3) * 2;
            float b0 = bias[col], b1 = bias[col + 1];
#pragma unroll
            for (int h2 = 0; h2 < 2; h2++) {
                int r = row + h2 * 8;
                float v0 = (c[i][j][2 * h2]     + b0) * outscale;
                float v1 = (c[i][j][2 * h2 + 1] + b1) * outscale;
                if (ysel < 3) {
                    float l0, l1;
                    float h0 = split_hi(v0, l0), h1 = split_hi(v1, l1);
                    Yh[(size_t)r * 512 + (col >> 1)] = pk2(h0, h1);
                    Yl[(size_t)r * 512 + (col >> 1)] = pk2(l0, l1);
                } else {
                    float2 o; o.x = v0; o.y = v1;
                    *(float2*)(Yout + (size_t)r * D_MODEL + col) = o;
                }
            }
        }
    }
}

// ---------------- Flash attention (HMMA, split bf16) -------------------------
// 128 q rows x 64 keys per tile; 4 warps, each m32. smem pitch 36 u32 (72 bf16).
#define FP 36

__global__ __launch_bounds__(128)
void flash_kernel()
{
    extern __shared__ u32 fsm[];
    u32* Qh = fsm;                 // 128*36
    u32* Ql = Qh + 128 * FP;
    u32* Kh = Ql + 128 * FP;       // 64*36
    u32* Kl = Kh + 64 * FP;
    u32* Vh = Kl + 64 * FP;        // transposed [d][key], 64*36
    u32* Vl = Vh + 64 * FP;

    int tid = threadIdx.x;
    int lane = tid & 31;
    int w = tid >> 5;
    int b = blockIdx.z, h = blockIdx.y;
    int qb = blockIdx.x * 128;

    // ---- load Q tile (bf16 pairs) ----
    {
        int row = tid;  // 128 rows
        const u32* srcH = g_Qh + (size_t)(b * SEQ + qb + row) * 512 + h * 32;
        const u32* srcL = g_Ql + (size_t)(b * SEQ + qb + row) * 512 + h * 32;
#pragma unroll
        for (int j = 0; j < 8; j++) {
            *(uint4*)&Qh[row * FP + 4 * j] = *(const uint4*)(srcH + 4 * j);
            *(uint4*)&Ql[row * FP + 4 * j] = *(const uint4*)(srcL + 4 * j);
        }
    }

    float s[2][8][4], o[2][8][4], m_[4], l_[4];
#pragma unroll
    for (int i = 0; i < 2; i++)
#pragma unroll
        for (int j = 0; j < 8; j++)
#pragma unroll
            for (int e = 0; e < 4; e++) o[i][j][e] = 0.f;
#pragma unroll
    for (int i = 0; i < 4; i++) { m_[i] = -1e30f; l_[i] = 0.f; }

    __nv_bfloat16* Vhb = reinterpret_cast<__nv_bfloat16*>(Vh);
    __nv_bfloat16* Vlb = reinterpret_cast<__nv_bfloat16*>(Vl);

    for (int kt = 0; kt < SEQ; kt += 64) {
        __syncthreads();
        // ---- load K tile ----
        {
            int r = tid >> 1, half = tid & 1;
            const u32* srcH = g_Kh + (size_t)(b * SEQ + kt + r) * 512 + h * 32 + half * 16;
            const u32* srcL = g_Kl + (size_t)(b * SEQ + kt + r) * 512 + h * 32 + half * 16;
#pragma unroll
            for (int j = 0; j < 4; j++) {
                *(uint4*)&Kh[r * FP + half * 16 + 4 * j] = *(const uint4*)(srcH + 4 * j);
                *(uint4*)&Kl[r * FP + half * 16 + 4 * j] = *(const uint4*)(srcL + 4 * j);
            }
        }
        // ---- load + transpose V tile: Vt[d][key] ----
        {
            int key = tid >> 1, half = tid & 1;
            const u32* srcH = g_Vh + (size_t)(b * SEQ + kt + key) * 512 + h * 32 + half * 16;
            const u32* srcL = g_Vl + (size_t)(b * SEQ + kt + key) * 512 + h * 32 + half * 16;
#pragma unroll
            for (int j = 0; j < 16; j++) {
                u32 ph = srcH[j], pl = srcL[j];
                int d0 = (half * 16 + j) * 2;
                __nv_bfloat162 vh2 = *reinterpret_cast<__nv_bfloat162*>(&ph);
                __nv_bfloat162 vl2 = *reinterpret_cast<__nv_bfloat162*>(&pl);
                Vhb[(d0    ) * 72 + key] = vh2.x;
                Vhb[(d0 + 1) * 72 + key] = vh2.y;
                Vlb[(d0    ) * 72 + key] = vl2.x;
                Vlb[(d0 + 1) * 72 + key] = vl2.y;
            }
        }
        __syncthreads();

        // ---- S = Q K^T ----
#pragma unroll
        for (int i = 0; i < 2; i++)
#pragma unroll
            for (int j = 0; j < 8; j++)
#pragma unroll
                for (int e = 0; e < 4; e++) s[i][j][e] = 0.f;

#pragma unroll
        for (int ks = 0; ks < 4; ks++) {
            int qw = (w * 32 + (lane >> 2)) * FP + ks * 8 + (lane & 3);
            u32 qhf[2][4], qlf[2][4];
#pragma unroll
            for (int i = 0; i < 2; i++) {
                int b0 = qw + i * 16 * FP;
                qhf[i][0] = Qh[b0];           qhf[i][1] = Qh[b0 + 8 * FP];
                qhf[i][2] = Qh[b0 + 4];       qhf[i][3] = Qh[b0 + 8 * FP + 4];
                qlf[i][0] = Ql[b0];           qlf[i][1] = Ql[b0 + 8 * FP];
                qlf[i][2] = Ql[b0 + 4];       qlf[i][3] = Ql[b0 + 8 * FP + 4];
            }
            int kw = (lane >> 2) * FP + ks * 8 + (lane & 3);
#pragma unroll
            for (int j = 0; j < 8; j++) {
                int b0 = kw + j * 8 * FP;
                u32 bh0 = Kh[b0], bh1 = Kh[b0 + 4];
                u32 bl0 = Kl[b0], bl1 = Kl[b0 + 4];
#pragma unroll
                for (int i = 0; i < 2; i++) {
                    mma16816(s[i][j], qhf[i][0], qhf[i][1], qhf[i][2], qhf[i][3], bh0, bh1);
                    mma16816(s[i][j], qhf[i][0], qhf[i][1], qhf[i][2], qhf[i][3], bl0, bl1);
                    mma16816(s[i][j], qlf[i][0], qlf[i][1], qlf[i][2], qlf[i][3], bh0, bh1);
                }
            }
        }

        // ---- online softmax ----
#pragma unroll
        for (int i = 0; i < 2; i++) {
#pragma unroll
            for (int h2 = 0; h2 < 2; h2++) {
                int ri = i * 2 + h2;
                float mx = -1e30f;
#pragma unroll
                for (int j = 0; j < 8; j++)
                    mx = fmaxf(mx, fmaxf(s[i][j][2 * h2], s[i][j][2 * h2 + 1]));
                mx = fmaxf(mx, __shfl_xor_sync(0xffffffffu, mx, 1));
                mx = fmaxf(mx, __shfl_xor_sync(0xffffffffu, mx, 2));
                float mn = fmaxf(m_[ri], mx);
                float alpha = __expf(m_[ri] - mn);
                m_[ri] = mn;
                float rs = 0.f;
#pragma unroll
                for (int j = 0; j < 8; j++) {
#pragma unroll
                    for (int e = 0; e < 2; e++) {
                        float p = __expf(s[i][j][2 * h2 + e] - mn);
                        s[i][j][2 * h2 + e] = p;
                        rs += p;
                    }
                }
                rs += __shfl_xor_sync(0xffffffffu, rs, 1);
                rs += __shfl_xor_sync(0xffffffffu, rs, 2);
                l_[ri] = l_[ri] * alpha + rs;
#pragma unroll
                for (int j = 0; j < 8; j++) {
                    o[i][j][2 * h2]     *= alpha;
                    o[i][j][2 * h2 + 1] *= alpha;
                }
            }
        }

        // ---- O += P V  (P fragments built in registers) ----
#pragma unroll
        for (int k2 = 0; k2 < 4; k2++) {
            u32 pah[2][4], pal[2][4];
#pragma unroll
            for (int i = 0; i < 2; i++) {
                float lo0, lo1;
                float h0, h1;
                h0 = split_hi(s[i][2 * k2][0], lo0);
                h1 = split_hi(s[i][2 * k2][1], lo1);
                pah[i][0] = pk2(h0, h1); pal[i][0] = pk2(lo0, lo1);
                h0 = split_hi(s[i][2 * k2][2], lo0);
                h1 = split_hi(s[i][2 * k2][3], lo1);
                pah[i][1] = pk2(h0, h1); pal[i][1] = pk2(lo0, lo1);
                h0 = split_hi(s[i][2 * k2 + 1][0], lo0);
                h1 = split_hi(s[i][2 * k2 + 1][1], lo1);
                pah[i][2] = pk2(h0, h1); pal[i][2] = pk2(lo0, lo1);
                h0 = split_hi(s[i][2 * k2 + 1][2], lo0);
                h1 = split_hi(s[i][2 * k2 + 1][3], lo1);
                pah[i][3] = pk2(h0, h1); pal[i][3] = pk2(lo0, lo1);
            }
#pragma unroll
            for (int jd = 0; jd < 8; jd++) {
                int vw = (jd * 8 + (lane >> 2)) * FP + k2 * 8 + (lane & 3);
                u32 bh0 = Vh[vw], bh1 = Vh[vw + 4];
                u32 bl0 = Vl[vw], bl1 = Vl[vw + 4];
#pragma unroll
                for (int i = 0; i < 2; i++) {
                    mma16816(o[i][jd], pah[i][0], pah[i][1], pah[i][2], pah[i][3], bh0, bh1);
                    mma16816(o[i][jd], pah[i][0], pah[i][1], pah[i][2], pah[i][3], bl0, bl1);
                    mma16816(o[i][jd], pal[i][0], pal[i][1], pal[i][2], pal[i][3], bh0, bh1);
                }
            }
        }
    }

    // ---- normalize + write AO fp32 [b, s, h*64+d] ----
#pragma unroll
    for (int i = 0; i < 2; i++) {
#pragma unroll
        for (int h2 = 0; h2 < 2; h2++) {
            float inv = 1.f / l_[i * 2 + h2];
            int row = qb + w * 32 + i * 16 + (lane >> 2) + h2 * 8;
            float* dst = g_AO + (size_t)(b * SEQ + row) * D_MODEL + h * DH + (lane & 3) * 2;
#pragma unroll
            for (int jd = 0; jd < 8; jd++) {
                float2 r;
                r.x = o[i][jd][2 * h2] * inv;
                r.y = o[i][jd][2 * h2 + 1] * inv;
                *(float2*)(dst + jd * 8) = r;
            }
        }
    }
}

// ---------------- launch ------------------------------------------------------
extern "C" void kernel_launch(void* const* d_in, const int* in_sizes, int n_in,
                              void* d_out, int out_size)
{
    (void)in_sizes; (void)n_in; (void)out_size;
    const float* query = (const float*)d_in[0];
    const float* key   = (const float*)d_in[1];
    const float* value = (const float*)d_in[2];

    cudaFuncSetAttribute(flash_kernel,
                         cudaFuncAttributeMaxDynamicSharedMemorySize, 73728);

    build_w_kernel<<<2048, 256>>>((const float*)d_in[3],  (const float*)d_in[4],  0);
    build_w_kernel<<<2048, 256>>>((const float*)d_in[6],  (const float*)d_in[7],  1);
    build_w_kernel<<<2048, 256>>>((const float*)d_in[9],  (const float*)d_in[10], 2);
    build_w_kernel<<<2048, 256>>>((const float*)d_in[12], (const float*)d_in[13], 3);

    dim3 gg(8, 32);
    gemm_kernel<<<gg, 256>>>(query, 0, 0, (const float*)d_in[5],  0.125f, nullptr, 0);
    gemm_kernel<<<gg, 256>>>(key,   1, 1, (const float*)d_in[8],  1.0f,   nullptr, 1);
    gemm_kernel<<<gg, 256>>>(value, 2, 2, (const float*)d_in[11], 1.0f,   nullptr, 2);

    flash_kernel<<<dim3(SEQ / 128, NH, BATCH), 128, 73728>>>();

    gemm_kernel<<<gg, 256>>>(nullptr, 3, 3, (const float*)d_in[14], 1.0f,
                             (float*)d_out, 3);
}

// round 14
// speedup vs baseline: 2.2908x; 1.0693x over previous
#include <cuda_runtime.h>
#include <cuda_bf16.h>

#define D_MODEL 1024
#define SEQ     2048
#define BATCH   2
#define NH      16
#define DH      64
#define MROWS   4096

typedef unsigned int u32;

// ---------------- helpers ----------------------------------------------------
__device__ __forceinline__ u32 pk2(float lo, float hi) {
    __nv_bfloat162 t = __floats2bfloat162_rn(lo, hi);   // lo -> .x (low half)
    return *reinterpret_cast<u32*>(&t);
}
__device__ __forceinline__ float split_hi(float x, float& lo) {
    float h = __bfloat162float(__float2bfloat16(x));
    lo = x - h;
    return h;
}
__device__ __forceinline__ void mma16816(float* c,
                                         u32 a0, u32 a1, u32 a2, u32 a3,
                                         u32 b0, u32 b1) {
    asm volatile(
        "mma.sync.aligned.m16n8k16.row.col.f32.bf16.bf16.f32 "
        "{%0,%1,%2,%3},{%4,%5,%6,%7},{%8,%9},{%0,%1,%2,%3};"
        : "+f"(c[0]), "+f"(c[1]), "+f"(c[2]), "+f"(c[3])
        : "r"(a0), "r"(a1), "r"(a2), "r"(a3), "r"(b0), "r"(b1));
}

// ---------------- scratch (static; no runtime allocation) --------------------
// bf16 PAIRS packed in u32: index = row*512 + col/2
__device__ u32 g_Wh[4][D_MODEL * 512];
__device__ u32 g_Wl[4][D_MODEL * 512];
__device__ u32 g_Qh[MROWS * 512], g_Ql[MROWS * 512];
__device__ u32 g_Kh[MROWS * 512], g_Kl[MROWS * 512];
__device__ u32 g_Vh[MROWS * 512], g_Vl[MROWS * 512];
__device__ float g_AO[MROWS * D_MODEL];

// ---------------- TT cores -> dense W (split bf16 hi/lo) ---------------------
__global__ void build_w_kernel(const float* __restrict__ g0,
                               const float* __restrict__ g1,
                               int wsel)
{
    int idx = blockIdx.x * 256 + threadIdx.x;   // over 1024*512 pairs
    int n  = idx >> 9;
    int k  = (idx & 511) * 2;
    int i1 = n >> 5, i2 = n & 31;
    int j1 = k >> 5, j2 = k & 31;
    const float* a = &g0[(i1 * 32 + j1) * 8];
    float s0 = 0.f, s1 = 0.f;
#pragma unroll
    for (int r = 0; r < 8; r++) {
        const float* g1p = &g1[(r * 32 + i2) * 32 + j2];
        s0 += a[r] * g1p[0];
        s1 += a[r] * g1p[1];
    }
    float l0, l1;
    float h0 = split_hi(s0, l0), h1 = split_hi(s1, l1);
    g_Wh[wsel][idx] = pk2(h0, h1);
    g_Wl[wsel][idx] = pk2(l0, l1);
}

// ---------------- GEMM: Y[M,1024] = X[M,1024] @ W^T + bias  (HMMA) ----------
// 128x128x32 tile, 256 threads = 8 warps of 64x32. Gmem prefetch double-buffer
// in registers; MMA sweeps term-outer so accumulator reuse distance is 16.
#define GP 20   /* smem row pitch in u32 pairs */

__global__ __launch_bounds__(256)
void gemm_kernel(const float* __restrict__ Xext, int xsel, int wsel,
                 const float* __restrict__ bias, float outscale,
                 float* __restrict__ Yout, int ysel)
{
    const float* X = (xsel == 3) ? g_AO : Xext;
    const u32* Wh = g_Wh[wsel];
    const u32* Wl = g_Wl[wsel];
    u32* Yh = (ysel == 0) ? g_Qh : (ysel == 1) ? g_Kh : g_Vh;
    u32* Yl = (ysel == 0) ? g_Ql : (ysel == 1) ? g_Kl : g_Vl;

    __shared__ u32 Ah[128 * GP], Al[128 * GP], Bh[128 * GP], Bl[128 * GP];

    int tid  = threadIdx.x;
    int lane = tid & 31;
    int warp = tid >> 5;
    int wm = warp & 1, wn = warp >> 1;
    int bm = blockIdx.y * 128, bn = blockIdx.x * 128;

    int lr = tid >> 1;          // 0..127 row
    int lh = tid & 1;           // k-half (16 k each)

    float c[4][4][4];
#pragma unroll
    for (int i = 0; i < 4; i++)
#pragma unroll
        for (int j = 0; j < 4; j++)
#pragma unroll
            for (int e = 0; e < 4; e++) c[i][j][e] = 0.f;

    const float* Xp = X + (size_t)(bm + lr) * D_MODEL + lh * 16;
    const u32* Whp = Wh + (size_t)(bn + lr) * 512 + lh * 8;
    const u32* Wlp = Wl + (size_t)(bn + lr) * 512 + lh * 8;
    u32* As_h = &Ah[lr * GP + lh * 8];
    u32* As_l = &Al[lr * GP + lh * 8];
    u32* Bs_h = &Bh[lr * GP + lh * 8];
    u32* Bs_l = &Bl[lr * GP + lh * 8];

    float4 xr[4];
    uint4 wrh[2], wrl[2];
#define LDG_TILE(K0)                                                        \
    {                                                                       \
        xr[0] = *(const float4*)(Xp + (K0));                                \
        xr[1] = *(const float4*)(Xp + (K0) + 4);                            \
        xr[2] = *(const float4*)(Xp + (K0) + 8);                            \
        xr[3] = *(const float4*)(Xp + (K0) + 12);                           \
        wrh[0] = *(const uint4*)(Whp + ((K0) >> 1));                        \
        wrh[1] = *(const uint4*)(Whp + ((K0) >> 1) + 4);                    \
        wrl[0] = *(const uint4*)(Wlp + ((K0) >> 1));                        \
        wrl[1] = *(const uint4*)(Wlp + ((K0) >> 1) + 4);                    \
    }

    LDG_TILE(0)

    for (int k0 = 0; k0 < D_MODEL; k0 += 32) {
        // split staged X, store staged tiles
        u32 hb[8], lb[8];
#pragma unroll
        for (int j = 0; j < 4; j++) {
            float l0, l1, l2, l3;
            float h0 = split_hi(xr[j].x, l0), h1 = split_hi(xr[j].y, l1);
            float h2 = split_hi(xr[j].z, l2), h3 = split_hi(xr[j].w, l3);
            hb[2 * j] = pk2(h0, h1); hb[2 * j + 1] = pk2(h2, h3);
            lb[2 * j] = pk2(l0, l1); lb[2 * j + 1] = pk2(l2, l3);
        }
        *(uint4*)(As_h)     = *(uint4*)&hb[0];
        *(uint4*)(As_h + 4) = *(uint4*)&hb[4];
        *(uint4*)(As_l)     = *(uint4*)&lb[0];
        *(uint4*)(As_l + 4) = *(uint4*)&lb[4];
        *(uint4*)(Bs_h)     = wrh[0];
        *(uint4*)(Bs_h + 4) = wrh[1];
        *(uint4*)(Bs_l)     = wrl[0];
        *(uint4*)(Bs_l + 4) = wrl[1];
        __syncthreads();

        // prefetch next k-slice (overlaps the MMA sweeps below)
        if (k0 + 32 < D_MODEL) LDG_TILE(k0 + 32)

#pragma unroll
        for (int ks = 0; ks < 2; ks++) {
            int aw = (wm * 64 + (lane >> 2)) * GP + ks * 8 + (lane & 3);
            u32 ah[4][4], al[4][4];
#pragma unroll
            for (int i = 0; i < 4; i++) {
                int b0 = aw + i * 16 * GP;
                ah[i][0] = Ah[b0];            ah[i][1] = Ah[b0 + 8 * GP];
                ah[i][2] = Ah[b0 + 4];        ah[i][3] = Ah[b0 + 8 * GP + 4];
                al[i][0] = Al[b0];            al[i][1] = Al[b0 + 8 * GP];
                al[i][2] = Al[b0 + 4];        al[i][3] = Al[b0 + 8 * GP + 4];
            }
            int bw = (wn * 32 + (lane >> 2)) * GP + ks * 8 + (lane & 3);
            u32 bh0[4], bh1[4], bl0[4], bl1[4];
#pragma unroll
            for (int j = 0; j < 4; j++) {
                int b0 = bw + j * 8 * GP;
                bh0[j] = Bh[b0]; bh1[j] = Bh[b0 + 4];
                bl0[j] = Bl[b0]; bl1[j] = Bl[b0 + 4];
            }
            // term sweeps: accumulator reuse distance = 16 MMAs
#pragma unroll
            for (int j = 0; j < 4; j++)
#pragma unroll
                for (int i = 0; i < 4; i++)
                    mma16816(c[i][j], ah[i][0], ah[i][1], ah[i][2], ah[i][3], bh0[j], bh1[j]);
#pragma unroll
            for (int j = 0; j < 4; j++)
#pragma unroll
                for (int i = 0; i < 4; i++)
                    mma16816(c[i][j], ah[i][0], ah[i][1], ah[i][2], ah[i][3], bl0[j], bl1[j]);
#pragma unroll
            for (int j = 0; j < 4; j++)
#pragma unroll
                for (int i = 0; i < 4; i++)
                    mma16816(c[i][j], al[i][0], al[i][1], al[i][2], al[i][3], bh0[j], bh1[j]);
        }
        __syncthreads();
    }

    // epilogue
#pragma unroll
    for (int i = 0; i < 4; i++) {
#pragma unroll
        for (int j = 0; j < 4; j++) {
            int row = bm + wm * 64 + i * 16 + (lane >> 2);
            int col = bn + wn * 32 + j * 8 + (lane & 3) * 2;
            float b0 = bias[col], b1 = bias[col + 1];
#pragma unroll
            for (int h2 = 0; h2 < 2; h2++) {
                int r = row + h2 * 8;
                float v0 = (c[i][j][2 * h2]     + b0) * outscale;
                float v1 = (c[i][j][2 * h2 + 1] + b1) * outscale;
                if (ysel < 3) {
                    float l0, l1;
                    float h0 = split_hi(v0, l0), h1 = split_hi(v1, l1);
                    Yh[(size_t)r * 512 + (col >> 1)] = pk2(h0, h1);
                    Yl[(size_t)r * 512 + (col >> 1)] = pk2(l0, l1);
                } else {
                    float2 o; o.x = v0; o.y = v1;
                    *(float2*)(Yout + (size_t)r * D_MODEL + col) = o;
                }
            }
        }
    }
}

// ---------------- Flash attention (HMMA, split bf16) -------------------------
// 128 q rows x 64 keys per tile; 256 threads = 8 warps, each m16.
// B-fragments preloaded to register arrays; MMA sweeps term-outer
// (accumulator reuse distance 8).
#define FP 36

__global__ __launch_bounds__(256)
void flash_kernel()
{
    extern __shared__ u32 fsm[];
    u32* Qh = fsm;                 // 128*FP
    u32* Ql = Qh + 128 * FP;
    u32* Kh = Ql + 128 * FP;       // 64*FP
    u32* Kl = Kh + 64 * FP;
    u32* Vh = Kl + 64 * FP;        // transposed [d][key], 64*FP
    u32* Vl = Vh + 64 * FP;

    int tid = threadIdx.x;
    int lane = tid & 31;
    int w = tid >> 5;               // 0..7, warp's 16-row q block
    int b = blockIdx.z, h = blockIdx.y;
    int qb = blockIdx.x * 128;

    // ---- load Q tile ----
    {
        int row = tid >> 1, half = tid & 1;
        const u32* srcH = g_Qh + (size_t)(b * SEQ + qb + row) * 512 + h * 32 + half * 16;
        const u32* srcL = g_Ql + (size_t)(b * SEQ + qb + row) * 512 + h * 32 + half * 16;
#pragma unroll
        for (int j = 0; j < 4; j++) {
            *(uint4*)&Qh[row * FP + half * 16 + 4 * j] = *(const uint4*)(srcH + 4 * j);
            *(uint4*)&Ql[row * FP + half * 16 + 4 * j] = *(const uint4*)(srcL + 4 * j);
        }
    }

    float s[8][4], o[8][4], m_[2], l_[2];
#pragma unroll
    for (int j = 0; j < 8; j++)
#pragma unroll
        for (int e = 0; e < 4; e++) o[j][e] = 0.f;
    m_[0] = m_[1] = -1e30f;
    l_[0] = l_[1] = 0.f;

    __nv_bfloat16* Vhb = reinterpret_cast<__nv_bfloat16*>(Vh);
    __nv_bfloat16* Vlb = reinterpret_cast<__nv_bfloat16*>(Vl);

    for (int kt = 0; kt < SEQ; kt += 64) {
        __syncthreads();
        // ---- load K tile ----
        {
            int r = tid >> 2, q4 = tid & 3;
            const u32* srcH = g_Kh + (size_t)(b * SEQ + kt + r) * 512 + h * 32 + q4 * 8;
            const u32* srcL = g_Kl + (size_t)(b * SEQ + kt + r) * 512 + h * 32 + q4 * 8;
            *(uint4*)&Kh[r * FP + q4 * 8]     = *(const uint4*)(srcH);
            *(uint4*)&Kh[r * FP + q4 * 8 + 4] = *(const uint4*)(srcH + 4);
            *(uint4*)&Kl[r * FP + q4 * 8]     = *(const uint4*)(srcL);
            *(uint4*)&Kl[r * FP + q4 * 8 + 4] = *(const uint4*)(srcL + 4);
        }
        // ---- load + transpose V tile: Vt[d][key] ----
        {
            int key = tid >> 2, q4 = tid & 3;
            const u32* srcH = g_Vh + (size_t)(b * SEQ + kt + key) * 512 + h * 32 + q4 * 8;
            const u32* srcL = g_Vl + (size_t)(b * SEQ + kt + key) * 512 + h * 32 + q4 * 8;
#pragma unroll
            for (int j = 0; j < 8; j++) {
                u32 ph = srcH[j], pl = srcL[j];
                int d0 = (q4 * 8 + j) * 2;
                __nv_bfloat162 vh2 = *reinterpret_cast<__nv_bfloat162*>(&ph);
                __nv_bfloat162 vl2 = *reinterpret_cast<__nv_bfloat162*>(&pl);
                Vhb[(d0    ) * 72 + key] = vh2.x;
                Vhb[(d0 + 1) * 72 + key] = vh2.y;
                Vlb[(d0    ) * 72 + key] = vl2.x;
                Vlb[(d0 + 1) * 72 + key] = vl2.y;
            }
        }
        __syncthreads();

        // ---- S = Q K^T ----
#pragma unroll
        for (int j = 0; j < 8; j++)
#pragma unroll
            for (int e = 0; e < 4; e++) s[j][e] = 0.f;

#pragma unroll
        for (int ks = 0; ks < 4; ks++) {
            int qw = (w * 16 + (lane >> 2)) * FP + ks * 8 + (lane & 3);
            u32 qh0 = Qh[qw], qh1 = Qh[qw + 8 * FP], qh2 = Qh[qw + 4], qh3 = Qh[qw + 8 * FP + 4];
            u32 ql0 = Ql[qw], ql1 = Ql[qw + 8 * FP], ql2 = Ql[qw + 4], ql3 = Ql[qw + 8 * FP + 4];
            int kw = (lane >> 2) * FP + ks * 8 + (lane & 3);
            u32 kb[8][4];
#pragma unroll
            for (int j = 0; j < 8; j++) {
                int b0 = kw + j * 8 * FP;
                kb[j][0] = Kh[b0]; kb[j][1] = Kh[b0 + 4];
                kb[j][2] = Kl[b0]; kb[j][3] = Kl[b0 + 4];
            }
#pragma unroll
            for (int j = 0; j < 8; j++)
                mma16816(s[j], qh0, qh1, qh2, qh3, kb[j][0], kb[j][1]);
#pragma unroll
            for (int j = 0; j < 8; j++)
                mma16816(s[j], qh0, qh1, qh2, qh3, kb[j][2], kb[j][3]);
#pragma unroll
            for (int j = 0; j < 8; j++)
                mma16816(s[j], ql0, ql1, ql2, ql3, kb[j][0], kb[j][1]);
        }

        // ---- online softmax (rows: lane>>2 and +8) ----
#pragma unroll
        for (int h2 = 0; h2 < 2; h2++) {
            float mx = -1e30f;
#pragma unroll
            for (int j = 0; j < 8; j++)
                mx = fmaxf(mx, fmaxf(s[j][2 * h2], s[j][2 * h2 + 1]));
            mx = fmaxf(mx, __shfl_xor_sync(0xffffffffu, mx, 1));
            mx = fmaxf(mx, __shfl_xor_sync(0xffffffffu, mx, 2));
            float mn = fmaxf(m_[h2], mx);
            float alpha = __expf(m_[h2] - mn);
            m_[h2] = mn;
            float rs = 0.f;
#pragma unroll
            for (int j = 0; j < 8; j++) {
#pragma unroll
                for (int e = 0; e < 2; e++) {
                    float p = __expf(s[j][2 * h2 + e] - mn);
                    s[j][2 * h2 + e] = p;
                    rs += p;
                }
            }
            rs += __shfl_xor_sync(0xffffffffu, rs, 1);
            rs += __shfl_xor_sync(0xffffffffu, rs, 2);
            l_[h2] = l_[h2] * alpha + rs;
#pragma unroll
            for (int j = 0; j < 8; j++) {
                o[j][2 * h2]     *= alpha;
                o[j][2 * h2 + 1] *= alpha;
            }
        }

        // ---- O += P V ----
#pragma unroll
        for (int k2 = 0; k2 < 4; k2++) {
            u32 pah[4], pal[4];
            {
                float lo0, lo1, h0, h1;
                h0 = split_hi(s[2 * k2][0], lo0);
                h1 = split_hi(s[2 * k2][1], lo1);
                pah[0] = pk2(h0, h1); pal[0] = pk2(lo0, lo1);
                h0 = split_hi(s[2 * k2][2], lo0);
                h1 = split_hi(s[2 * k2][3], lo1);
                pah[1] = pk2(h0, h1); pal[1] = pk2(lo0, lo1);
                h0 = split_hi(s[2 * k2 + 1][0], lo0);
                h1 = split_hi(s[2 * k2 + 1][1], lo1);
                pah[2] = pk2(h0, h1); pal[2] = pk2(lo0, lo1);
                h0 = split_hi(s[2 * k2 + 1][2], lo0);
                h1 = split_hi(s[2 * k2 + 1][3], lo1);
                pah[3] = pk2(h0, h1); pal[3] = pk2(lo0, lo1);
            }
            u32 vb[8][4];
#pragma unroll
            for (int jd = 0; jd < 8; jd++) {
                int vw = (jd * 8 + (lane >> 2)) * FP + k2 * 8 + (lane & 3);
                vb[jd][0] = Vh[vw]; vb[jd][1] = Vh[vw + 4];
                vb[jd][2] = Vl[vw]; vb[jd][3] = Vl[vw + 4];
            }
#pragma unroll
            for (int jd = 0; jd < 8; jd++)
                mma16816(o[jd], pah[0], pah[1], pah[2], pah[3], vb[jd][0], vb[jd][1]);
#pragma unroll
            for (int jd = 0; jd < 8; jd++)
                mma16816(o[jd], pah[0], pah[1], pah[2], pah[3], vb[jd][2], vb[jd][3]);
#pragma unroll
            for (int jd = 0; jd < 8; jd++)
                mma16816(o[jd], pal[0], pal[1], pal[2], pal[3], vb[jd][0], vb[jd][1]);
        }
    }

    // ---- normalize + write AO fp32 [b, s, h*64+d] ----
#pragma unroll
    for (int h2 = 0; h2 < 2; h2++) {
        float inv = 1.f / l_[h2];
        int row = qb + w * 16 + (lane >> 2) + h2 * 8;
        float* dst = g_AO + (size_t)(b * SEQ + row) * D_MODEL + h * DH + (lane & 3) * 2;
#pragma unroll
        for (int jd = 0; jd < 8; jd++) {
            float2 r;
            r.x = o[jd][2 * h2] * inv;
            r.y = o[jd][2 * h2 + 1] * inv;
            *(float2*)(dst + jd * 8) = r;
        }
    }
}

// ---------------- launch ------------------------------------------------------
extern "C" void kernel_launch(void* const* d_in, const int* in_sizes, int n_in,
                              void* d_out, int out_size)
{
    (void)in_sizes; (void)n_in; (void)out_size;
    const float* query = (const float*)d_in[0];
    const float* key   = (const float*)d_in[1];
    const float* value = (const float*)d_in[2];

    cudaFuncSetAttribute(flash_kernel,
                         cudaFuncAttributeMaxDynamicSharedMemorySize, 73728);

    build_w_kernel<<<2048, 256>>>((const float*)d_in[3],  (const float*)d_in[4],  0);
    build_w_kernel<<<2048, 256>>>((const float*)d_in[6],  (const float*)d_in[7],  1);
    build_w_kernel<<<2048, 256>>>((const float*)d_in[9],  (const float*)d_in[10], 2);
    build_w_kernel<<<2048, 256>>>((const float*)d_in[12], (const float*)d_in[13], 3);

    dim3 gg(8, 32);
    gemm_kernel<<<gg, 256>>>(query, 0, 0, (const float*)d_in[5],  0.125f, nullptr, 0);
    gemm_kernel<<<gg, 256>>>(key,   1, 1, (const float*)d_in[8],  1.0f,   nullptr, 1);
    gemm_kernel<<<gg, 256>>>(value, 2, 2, (const float*)d_in[11], 1.0f,   nullptr, 2);

    flash_kernel<<<dim3(SEQ / 128, NH, BATCH), 256, 73728>>>();

    gemm_kernel<<<gg, 256>>>(nullptr, 3, 3, (const float*)d_in[14], 1.0f,
                             (float*)d_out, 3);
}